// round 8
// baseline (speedup 1.0000x reference)
#include <cuda_runtime.h>

// AdvectionDiffusionReaction2M — temporal-blocked stencil.
// Round-4 tiling (ext 64x64, owned 48x48, redundancy 1.78x, 121 blocks, S=8,
// 25 launches) but with 512-thread blocks: thread tile 2 rows x 4 cols.
// Same total instruction volume as round 4, 2x warps/SMSP for latency hiding
// (round-7 evidence: kernel is latency-bound, not throughput-bound).

#define NN     512
#define N2     (NN * NN)
#define S      8
#define TILEW  48
#define EXT    64
#define NSTEPS 199

template <int NS>
__global__ __launch_bounds__(512)
void adr_chunk_kernel(const float* __restrict__ src,
                      float*       __restrict__ out,
                      int t0,
                      const float* __restrict__ k1p,
                      const float* __restrict__ k2p,
                      const float* __restrict__ a1p,
                      const float* __restrict__ a2p)
{
    // double-buffered strip-boundary rows; strip ty+1, pads at 0 and 33
    __shared__ float s_top[2][34][EXT];
    __shared__ float s_bot[2][34][EXT];

    const int tx = threadIdx.x;   // 0..15, cols 4tx..4tx+3 of ext tile
    const int ty = threadIdx.y;   // 0..31, rows 2ty..2ty+1

    const int ro0 = blockIdx.y * TILEW;
    const int co0 = blockIdx.x * TILEW;
    const int gi0 = ro0 - S + 2 * ty;
    const int gj0 = co0 - S + 4 * tx;

    const float k1 = __ldg(k1p), k2 = __ldg(k2p);
    const float a1 = __ldg(a1p), a2 = __ldg(a2p);
    const float inv_ksum = 1.0f / (k1 + k2);

    const float dx2f   = (float)((1.0 / 511.0) * (1.0 / 511.0));
    const float twodxf = (float)(2.0 / 511.0);
    const float DT     = 1e-7f;

    // 4-col packs never straddle j=256 (256-(co0-8) divisible by 4)
    const float kap  = (gj0 < 256) ? k1 : k2;
    const float al   = (gj0 < 256) ? a1 : a2;
    const float c_al = DT * al / dx2f;
    const float cx   = DT * kap / twodxf;
    const float ck   = DT * kap;

    // ---- clamped initial load (field at step t0-1) ----
    float v[2][4];
    #pragma unroll
    for (int r = 0; r < 2; ++r) {
        const int gi = min(max(gi0 + r, 0), NN - 1);
        #pragma unroll
        for (int c = 0; c < 4; ++c) {
            const int gj = min(max(gj0 + c, 0), NN - 1);
            v[r][c] = src[gi * NN + gj];
        }
    }

    // intra-thread fixup / ownership flags (re-derived for 2-row strips)
    const bool ifc    = (gj0 + 3 == 255);                   // bx==5, tx==5
    const bool fix_rt = (blockIdx.y == 0  && ty == 4);      // row 0   <- row 1  : n[0]<-n[1]
    const bool fix_rb = (ro0 == 480       && ty == 19);     // row 511 <- row 510: n[1]<-n[0]
    const bool fix_cl = (blockIdx.x == 0  && tx == 2);      // col 0   <- col 1
    const bool fix_cr = (co0 == 480       && tx == 9);      // col 511 <- col 510
    const bool store_ok = (ty >= 4 && ty < 28) &&
                          (tx >= 2 && tx < 14) &&
                          (gi0 < NN) && (gj0 < NN);

    float* __restrict__ slab = out + (size_t)t0 * N2;
    const unsigned FULL = 0xffffffffu;

    #pragma unroll
    for (int k = 0; k < NS; ++k) {
        const int pb = k & 1;

        // ---- vertical boundary exchange (old values, 16B ops) ----
        *(float4*)&s_top[pb][ty + 1][4 * tx] = make_float4(v[0][0], v[0][1], v[0][2], v[0][3]);
        *(float4*)&s_bot[pb][ty + 1][4 * tx] = make_float4(v[1][0], v[1][1], v[1][2], v[1][3]);
        __syncthreads();
        const float4 upv = *(const float4*)&s_bot[pb][ty][4 * tx];       // row above strip
        const float4 dnv = *(const float4*)&s_top[pb][ty + 2][4 * tx];   // row below strip
        const float up[4] = {upv.x, upv.y, upv.z, upv.w};
        const float dn[4] = {dnv.x, dnv.y, dnv.z, dnv.w};

        // ---- horizontal pack edges (old values). Warp spans 2 ty rows;
        // shfl row-mixing only occurs at tx=0/15 = ext-tile rim (garbage ok).
        float lft[2], rgt[2];
        #pragma unroll
        for (int r = 0; r < 2; ++r) {
            lft[r] = __shfl_up_sync(FULL,   v[r][3], 1);
            rgt[r] = __shfl_down_sync(FULL, v[r][0], 1);
        }

        // ---- 8 cell updates ----
        float n[2][4];
        #pragma unroll
        for (int r = 0; r < 2; ++r) {
            #pragma unroll
            for (int c = 0; c < 4; ++c) {
                const float cu = v[r][c];
                const float u_ = (r == 0) ? up[c] : v[0][c];
                const float d_ = (r == 1) ? dn[c] : v[1][c];
                const float l_ = (c == 0) ? lft[r] : v[r][c - 1];
                const float r_ = (c == 3) ? rgt[r] : v[r][c + 1];

                const float sum  = (u_ + d_) + (l_ + r_);
                const float lap  = fmaf(-4.0f, cu, sum);
                const float A    = fmaf(cu, d_ - u_, l_ - r_);
                const float adv  = cu * A;
                const float q    = fmaf(cu, cu, -cu);
                const float reac = cu * (q + 1.0f);

                float val = fmaf(c_al, lap, cu);
                val = fmaf(-cx, adv, val);
                val = fmaf(ck, reac, val);
                n[r][c] = val;
            }
        }

        // ---- interface column j=255 (c==3 of tx==5), from OLD neighbors ----
        if (ifc) {
            n[0][3] = (k1 * rgt[0] + k2 * v[0][2]) * inv_ksum;
            n[1][3] = (k1 * rgt[1] + k2 * v[1][2]) * inv_ksum;
        }

        // ---- domain-edge fixups (rows then cols, matching reference order) ----
        if (fix_rt) { n[0][0] = n[1][0]; n[0][1] = n[1][1]; n[0][2] = n[1][2]; n[0][3] = n[1][3]; }
        if (fix_rb) { n[1][0] = n[0][0]; n[1][1] = n[0][1]; n[1][2] = n[0][2]; n[1][3] = n[0][3]; }
        if (fix_cl) { n[0][0] = n[0][1]; n[1][0] = n[1][1]; }
        if (fix_cr) { n[0][3] = n[0][2]; n[1][3] = n[1][2]; }

        // ---- store owned 2x4 pack (coalesced 16B stores) ----
        if (store_ok) {
            *(float4*)&slab[(size_t)(gi0    ) * NN + gj0] = make_float4(n[0][0], n[0][1], n[0][2], n[0][3]);
            *(float4*)&slab[(size_t)(gi0 + 1) * NN + gj0] = make_float4(n[1][0], n[1][1], n[1][2], n[1][3]);
        }

        slab += N2;
        #pragma unroll
        for (int r = 0; r < 2; ++r)
            #pragma unroll
            for (int c = 0; c < 4; ++c)
                v[r][c] = n[r][c];
    }
}

extern "C" void kernel_launch(void* const* d_in, const int* in_sizes, int n_in,
                              void* d_out, int out_size)
{
    const float* u0  = (const float*)d_in[0];
    const float* k1p = (const float*)d_in[1];
    const float* k2p = (const float*)d_in[2];
    const float* a1p = (const float*)d_in[3];
    const float* a2p = (const float*)d_in[4];
    float* out = (float*)d_out;

    dim3 block(16, 32, 1);
    dim3 grid((NN + TILEW - 1) / TILEW, (NN + TILEW - 1) / TILEW, 1);  // 11 x 11

    int t0 = 0;
    for (int c = 0; c < 24; ++c) {
        const float* src = (t0 == 0) ? u0 : (out + (size_t)(t0 - 1) * N2);
        adr_chunk_kernel<8><<<grid, block>>>(src, out, t0, k1p, k2p, a1p, a2p);
        t0 += 8;
    }
    {
        const float* src = out + (size_t)(t0 - 1) * N2;
        adr_chunk_kernel<7><<<grid, block>>>(src, out, t0, k1p, k2p, a1p, a2p);
    }
}

// round 9
// speedup vs baseline: 1.0760x; 1.0760x over previous
#include <cuda_runtime.h>

// AdvectionDiffusionReaction2M — temporal-blocked stencil.
// Round-4 per-thread shape (4x4 cells, minimal instr/cell) with SM-filling
// geometry: ext 64x56, owned 48x40, block (16,14)=224 thr, grid 11x13 = 143
// blocks (vs R4's 121) -> 97% SM coverage at +3.5% work. Level loop template-
// unrolled. S=8, 25 launches.
// Lessons: R6/R8 showed smaller thread tiles raise MIO work/cell and regress;
// R7 showed FMA-pipe width isn't the binding constraint.

#define NN     512
#define N2     (NN * NN)
#define S      8
#define OWNW   48
#define OWNH   40
#define EXTW   64
#define EXTH   56
#define NSTEPS 199

template <int NS>
__global__ __launch_bounds__(224)
void adr_chunk_kernel(const float* __restrict__ src,
                      float*       __restrict__ out,
                      int t0,
                      const float* __restrict__ k1p,
                      const float* __restrict__ k2p,
                      const float* __restrict__ a1p,
                      const float* __restrict__ a2p)
{
    // double-buffered strip-boundary rows; strip ty+1, pads at 0 and 15
    __shared__ float s_top[2][16][EXTW];
    __shared__ float s_bot[2][16][EXTW];

    const int tx = threadIdx.x;   // 0..15, cols 4tx..4tx+3 of ext tile
    const int ty = threadIdx.y;   // 0..13, rows 4ty..4ty+3

    const int ro0 = blockIdx.y * OWNH;       // by: 0..12 (last row truncated)
    const int co0 = blockIdx.x * OWNW;       // bx: 0..10
    const int gi0 = ro0 - S + 4 * ty;
    const int gj0 = co0 - S + 4 * tx;

    // zero the pad rows once (read at ty==0 / ty==13; values land in rim only)
    if (ty == 0) {
        s_top[0][0][tx] = 0.f; s_top[0][15][tx] = 0.f; s_top[0][0][tx+16] = 0.f; s_top[0][15][tx+16] = 0.f;
        s_top[0][0][tx+32] = 0.f; s_top[0][15][tx+32] = 0.f; s_top[0][0][tx+48] = 0.f; s_top[0][15][tx+48] = 0.f;
        s_top[1][0][tx] = 0.f; s_top[1][15][tx] = 0.f; s_top[1][0][tx+16] = 0.f; s_top[1][15][tx+16] = 0.f;
        s_top[1][0][tx+32] = 0.f; s_top[1][15][tx+32] = 0.f; s_top[1][0][tx+48] = 0.f; s_top[1][15][tx+48] = 0.f;
        s_bot[0][0][tx] = 0.f; s_bot[0][15][tx] = 0.f; s_bot[0][0][tx+16] = 0.f; s_bot[0][15][tx+16] = 0.f;
        s_bot[0][0][tx+32] = 0.f; s_bot[0][15][tx+32] = 0.f; s_bot[0][0][tx+48] = 0.f; s_bot[0][15][tx+48] = 0.f;
        s_bot[1][0][tx] = 0.f; s_bot[1][15][tx] = 0.f; s_bot[1][0][tx+16] = 0.f; s_bot[1][15][tx+16] = 0.f;
        s_bot[1][0][tx+32] = 0.f; s_bot[1][15][tx+32] = 0.f; s_bot[1][0][tx+48] = 0.f; s_bot[1][15][tx+48] = 0.f;
    }

    const float k1 = __ldg(k1p), k2 = __ldg(k2p);
    const float a1 = __ldg(a1p), a2 = __ldg(a2p);
    const float inv_ksum = 1.0f / (k1 + k2);

    const float dx2f   = (float)((1.0 / 511.0) * (1.0 / 511.0));
    const float twodxf = (float)(2.0 / 511.0);
    const float DT     = 1e-7f;

    // 4-col packs never straddle j=256
    const float kap  = (gj0 < 256) ? k1 : k2;
    const float al   = (gj0 < 256) ? a1 : a2;
    const float c_al = DT * al / dx2f;
    const float cx   = DT * kap / twodxf;
    const float ck   = DT * kap;

    // ---- clamped initial load (field at step t0-1) ----
    float v[4][4];
    #pragma unroll
    for (int r = 0; r < 4; ++r) {
        const int gi = min(max(gi0 + r, 0), NN - 1);
        #pragma unroll
        for (int c = 0; c < 4; ++c) {
            const int gj = min(max(gj0 + c, 0), NN - 1);
            v[r][c] = src[gi * NN + gj];
        }
    }

    // intra-thread fixup / ownership flags (re-derived for OWNH=40)
    const bool ifc    = (gj0 + 3 == 255);                  // bx==5, tx==5
    const bool fix_rt = (blockIdx.y == 0  && ty == 2);     // row 0   <- row 1  : n[0]<-n[1]
    const bool fix_rb = (ro0 == 480       && ty == 9);     // row 511 <- row 510: n[3]<-n[2]
    const bool fix_cl = (blockIdx.x == 0  && tx == 2);     // col 0   <- col 1
    const bool fix_cr = (co0 == 480       && tx == 9);     // col 511 <- col 510
    const bool store_ok = (ty >= 2 && ty < 12) &&
                          (tx >= 2 && tx < 14) &&
                          (gi0 < NN) && (gj0 < NN);

    float* __restrict__ slab = out + (size_t)t0 * N2;
    const unsigned FULL = 0xffffffffu;
    __syncthreads();   // pad zeroing visible before first level reads pads

    #pragma unroll
    for (int k = 0; k < NS; ++k) {
        const int pb = k & 1;

        // ---- vertical boundary exchange (old values, 16B ops) ----
        *(float4*)&s_top[pb][ty + 1][4 * tx] = make_float4(v[0][0], v[0][1], v[0][2], v[0][3]);
        *(float4*)&s_bot[pb][ty + 1][4 * tx] = make_float4(v[3][0], v[3][1], v[3][2], v[3][3]);
        __syncthreads();
        const float4 upv = *(const float4*)&s_bot[pb][ty][4 * tx];       // row above strip
        const float4 dnv = *(const float4*)&s_top[pb][ty + 2][4 * tx];   // row below strip
        const float up[4] = {upv.x, upv.y, upv.z, upv.w};
        const float dn[4] = {dnv.x, dnv.y, dnv.z, dnv.w};

        // ---- horizontal pack edges (old values; 16-wide rows warp-aligned) ----
        float lft[4], rgt[4];
        #pragma unroll
        for (int r = 0; r < 4; ++r) {
            lft[r] = __shfl_up_sync(FULL,   v[r][3], 1);
            rgt[r] = __shfl_down_sync(FULL, v[r][0], 1);
        }

        // ---- 16 cell updates ----
        float n[4][4];
        #pragma unroll
        for (int r = 0; r < 4; ++r) {
            #pragma unroll
            for (int c = 0; c < 4; ++c) {
                const float cu = v[r][c];
                const float u_ = (r == 0) ? up[c] : v[r - 1][c];
                const float d_ = (r == 3) ? dn[c] : v[r + 1][c];
                const float l_ = (c == 0) ? lft[r] : v[r][c - 1];
                const float r_ = (c == 3) ? rgt[r] : v[r][c + 1];

                const float sum  = (u_ + d_) + (l_ + r_);
                const float lap  = fmaf(-4.0f, cu, sum);
                const float A    = fmaf(cu, d_ - u_, l_ - r_);
                const float adv  = cu * A;
                const float q    = fmaf(cu, cu, -cu);
                const float reac = cu * (q + 1.0f);

                float val = fmaf(c_al, lap, cu);
                val = fmaf(-cx, adv, val);
                val = fmaf(ck, reac, val);
                n[r][c] = val;
            }
        }

        // ---- interface column j=255 (c==3 of tx==5), from OLD neighbors ----
        if (ifc) {
            #pragma unroll
            for (int r = 0; r < 4; ++r)
                n[r][3] = (k1 * rgt[r] + k2 * v[r][2]) * inv_ksum;
        }

        // ---- domain-edge fixups (rows then cols, matching reference order) ----
        if (fix_rt) { n[0][0] = n[1][0]; n[0][1] = n[1][1]; n[0][2] = n[1][2]; n[0][3] = n[1][3]; }
        if (fix_rb) { n[3][0] = n[2][0]; n[3][1] = n[2][1]; n[3][2] = n[2][2]; n[3][3] = n[2][3]; }
        if (fix_cl) { n[0][0] = n[0][1]; n[1][0] = n[1][1]; n[2][0] = n[2][1]; n[3][0] = n[3][1]; }
        if (fix_cr) { n[0][3] = n[0][2]; n[1][3] = n[1][2]; n[2][3] = n[2][2]; n[3][3] = n[3][2]; }

        // ---- store owned 4x4 (coalesced 16B stores) ----
        if (store_ok) {
            #pragma unroll
            for (int r = 0; r < 4; ++r)
                *(float4*)&slab[(size_t)(gi0 + r) * NN + gj0] =
                    make_float4(n[r][0], n[r][1], n[r][2], n[r][3]);
        }

        slab += N2;
        #pragma unroll
        for (int r = 0; r < 4; ++r)
            #pragma unroll
            for (int c = 0; c < 4; ++c)
                v[r][c] = n[r][c];
    }
}

extern "C" void kernel_launch(void* const* d_in, const int* in_sizes, int n_in,
                              void* d_out, int out_size)
{
    const float* u0  = (const float*)d_in[0];
    const float* k1p = (const float*)d_in[1];
    const float* k2p = (const float*)d_in[2];
    const float* a1p = (const float*)d_in[3];
    const float* a2p = (const float*)d_in[4];
    float* out = (float*)d_out;

    dim3 block(16, 14, 1);
    dim3 grid((NN + OWNW - 1) / OWNW, (NN + OWNH - 1) / OWNH, 1);  // 11 x 13 = 143

    int t0 = 0;
    for (int c = 0; c < 24; ++c) {
        const float* src = (t0 == 0) ? u0 : (out + (size_t)(t0 - 1) * N2);
        adr_chunk_kernel<8><<<grid, block>>>(src, out, t0, k1p, k2p, a1p, a2p);
        t0 += 8;
    }
    {
        const float* src = out + (size_t)(t0 - 1) * N2;
        adr_chunk_kernel<7><<<grid, block>>>(src, out, t0, k1p, k2p, a1p, a2p);
    }
}